// round 11
// baseline (speedup 1.0000x reference)
#include <cuda_runtime.h>

// SNN forward: T=1000, B=8192, I=9, H=96, O=3
// 4 batches/warp (2 independent batch-sets = 2x ILP), 16 weight lanes.
// CTA = 64 threads (2 warps), grid = 1024 -> single wave (7 CTAs/SM).
// v = beta*mem1 + b1 - spk1 state fusion; reduction split across iterations.
// Spikes via set.gt.f32.f32 (one FSET). x rows read as plain C++ ulonglong2
// (LDS.128) so the compiler models the shared-memory dependency correctly
// (the previous inline-asm LDS lacked a memory clobber -> stale-read race).

#define T_STEPS 1000
#define BATCHN  8192
#define BETA    0.92f

typedef unsigned long long u64;

static __device__ __forceinline__ u64 pk2(float lo, float hi) {
    u64 r; asm("mov.b64 %0,{%1,%2};" : "=l"(r) : "f"(lo), "f"(hi)); return r;
}
static __device__ __forceinline__ void upk2(u64 v, float& a, float& b) {
    asm("mov.b64 {%0,%1},%2;" : "=f"(a), "=f"(b) : "l"(v));
}
static __device__ __forceinline__ u64 ffma2(u64 a, u64 b, u64 c) {
    u64 d; asm("fma.rn.f32x2 %0,%1,%2,%3;" : "=l"(d) : "l"(a), "l"(b), "l"(c)); return d;
}
static __device__ __forceinline__ u64 fmul2(u64 a, u64 b) {
    u64 d; asm("mul.rn.f32x2 %0,%1,%2;" : "=l"(d) : "l"(a), "l"(b)); return d;
}
static __device__ __forceinline__ float setgt1(float a) {
    float d; asm("set.gt.f32.f32 %0,%1,%2;" : "=f"(d) : "f"(a), "f"(1.0f)); return d;
}

__global__ void __launch_bounds__(64, 7) snn_kernel(
    const float* __restrict__ x,
    const float* __restrict__ W1,
    const float* __restrict__ b1,
    const float* __restrict__ W2,
    const float* __restrict__ b2,
    float* __restrict__ out)
{
    const int lane = threadIdx.x & 31;
    const int warp = threadIdx.x >> 5;
    const int gw   = blockIdx.x * 2 + warp;
    const int grp  = lane >> 4;                  // batch slot within set (0/1)
    const int hl   = lane & 15;                  // hidden slice 0..15
    const int hb   = hl * 6;
    const int bA   = gw * 4 + grp;               // set-0 batch; set-1 = bA + 2

    // x staging ring: [warp][buf3][4 slots x 10 u64] (slot rows 16B aligned)
    __shared__ __align__(16) u64 xs[2][3][40];

    // ---- weights in registers (shared by both batch sets) ----
    u64 w1p[3][9];
    #pragma unroll
    for (int j = 0; j < 3; j++)
        #pragma unroll
        for (int i = 0; i < 9; i++)
            w1p[j][i] = pk2(W1[(hb + 2*j) * 9 + i], W1[(hb + 2*j + 1) * 9 + i]);

    u64 w2p[3][3];
    #pragma unroll
    for (int o = 0; o < 3; o++)
        #pragma unroll
        for (int j = 0; j < 3; j++)
            w2p[o][j] = pk2(W2[o * 96 + hb + 2*j], W2[o * 96 + hb + 2*j + 1]);

    u64 b1p[3];
    #pragma unroll
    for (int j = 0; j < 3; j++) b1p[j] = pk2(b1[hb + 2*j], b1[hb + 2*j + 1]);

    const u64 BET2 = pk2(BETA, BETA);
    const u64 NEG1 = pk2(-1.0f, -1.0f);

    // ---- finalize lane roles ----
    const int  oc        = (hl >> 2) > 2 ? 2 : (hl >> 2);
    const bool fin_store = ((hl & 3) < 2) && (hl < 12);
    const bool is_spk    = (hl & 3) == 0;
    const float bias     = b2[oc];

    float* optr = (is_spk ? out : out + (size_t)T_STEPS * BATCHN * 3)
                  + (size_t)bA * 3 + oc;         // set-1 target = optr + 6

    // ---- state per set:  v = beta*mem1 + b1 - spk1 ----
    u64 vA0 = b1p[0], vA1 = b1p[1], vA2 = b1p[2];
    u64 vB0 = b1p[0], vB1 = b1p[1], vB2 = b1p[2];
    float m2A = 0.f, spA = 0.f, ppA = 0.f;       // spA/spB: previous spk2 (0/1)
    float m2B = 0.f, spB = 0.f, ppB = 0.f;

    // ---- x loaders: 36 contiguous floats per warp-step ----
    const int  idx0 = lane;
    const int  off0 = (idx0 / 9) * 10 + idx0 % 9;
    const bool l2   = lane < 4;
    const int  idx1 = 32 + lane;
    const int  off1 = (idx1 / 9) * 10 + idx1 % 9;
    const float* p0 = x + (size_t)gw * 36 + idx0;
    const float* p1 = x + (size_t)gw * 36 + idx1;
    const size_t xstr = (size_t)BATCHN * 9;

    float r0 = p0[0];
    float r1 = l2 ? p1[0] : 0.f;
    xs[warp][0][off0] = pk2(r0, r0);
    if (l2) xs[warp][0][off1] = pk2(r1, r1);
    r0 = p0[xstr];
    r1 = l2 ? p1[xstr] : 0.f;
    __syncwarp();

    int bcur = 0, bnext = 1, bnn = 2;
    #pragma unroll 3
    for (int t = 0; t < T_STEPS; t++) {
        // ---- set-A x loads first (buffer written last iter, sync'd) ----
        u64 xpA[9];
        {
            const ulonglong2* q = reinterpret_cast<const ulonglong2*>(xs[warp][bcur] + grp * 10);
            ulonglong2 t0 = q[0], t1 = q[1], t2 = q[2], t3 = q[3];
            xpA[0] = t0.x; xpA[1] = t0.y;
            xpA[2] = t1.x; xpA[3] = t1.y;
            xpA[4] = t2.x; xpA[5] = t2.y;
            xpA[6] = t3.x; xpA[7] = t3.y;
            xpA[8] = xs[warp][bcur][grp * 10 + 8];
        }

        // ---- stage x(t+1), launch load of x(t+2) ----
        xs[warp][bnext][off0] = pk2(r0, r0);
        if (l2) xs[warp][bnext][off1] = pk2(r1, r1);
        {
            int tn = (t + 2 < T_STEPS) ? (t + 2) : (T_STEPS - 1);
            r0 = p0[(size_t)tn * xstr];
            r1 = l2 ? p1[(size_t)tn * xstr] : 0.f;
        }

        // ---- head: finish previous step's reductions + finalize + store ----
        if (t) {
            float svA = ppA, svB = ppB;
            svA += __shfl_xor_sync(0xffffffffu, svA, 2);
            svB += __shfl_xor_sync(0xffffffffu, svB, 2);
            svA += __shfl_xor_sync(0xffffffffu, svA, 1);
            svB += __shfl_xor_sync(0xffffffffu, svB, 1);
            float mmA = fmaf(BETA, m2A, bias + svA) - spA;  m2A = mmA;
            float mmB = fmaf(BETA, m2B, bias + svB) - spB;  m2B = mmB;
            spA = setgt1(mmA);
            spB = setgt1(mmB);
            if (fin_store) {
                __stcs(optr,     is_spk ? spA : mmA);
                __stcs(optr + 6, is_spk ? spB : mmB);
            }
            optr += 3 * BATCHN;
        }

        float sA0, sA1, sA2, sB0, sB1, sB2;

        // ======== batch set A ========
        {
            u64 a0 = vA0, a1 = vA1, a2 = vA2;
            #pragma unroll
            for (int i = 0; i < 9; i++) {
                a0 = ffma2(w1p[0][i], xpA[i], a0);
                a1 = ffma2(w1p[1][i], xpA[i], a1);
                a2 = ffma2(w1p[2][i], xpA[i], a2);
            }
            float f0, f1;
            upk2(a0, f0, f1);
            u64 s0 = pk2(setgt1(f0), setgt1(f1));
            upk2(a1, f0, f1);
            u64 s1 = pk2(setgt1(f0), setgt1(f1));
            upk2(a2, f0, f1);
            u64 s2 = pk2(setgt1(f0), setgt1(f1));
            vA0 = ffma2(BET2, a0, ffma2(s0, NEG1, b1p[0]));
            vA1 = ffma2(BET2, a1, ffma2(s1, NEG1, b1p[1]));
            vA2 = ffma2(BET2, a2, ffma2(s2, NEG1, b1p[2]));

            u64 c0 = fmul2(s0, w2p[0][0]); c0 = ffma2(s1, w2p[0][1], c0); c0 = ffma2(s2, w2p[0][2], c0);
            u64 c1 = fmul2(s0, w2p[1][0]); c1 = ffma2(s1, w2p[1][1], c1); c1 = ffma2(s2, w2p[1][2], c1);
            u64 c2 = fmul2(s0, w2p[2][0]); c2 = ffma2(s1, w2p[2][1], c2); c2 = ffma2(s2, w2p[2][2], c2);
            float ta, tb;
            upk2(c0, ta, tb); sA0 = ta + tb;
            upk2(c1, ta, tb); sA1 = ta + tb;
            upk2(c2, ta, tb); sA2 = ta + tb;
        }

        // ======== batch set B ========
        {
            u64 xp[9];
            {
                const ulonglong2* q = reinterpret_cast<const ulonglong2*>(xs[warp][bcur] + (grp + 2) * 10);
                ulonglong2 t0 = q[0], t1 = q[1], t2 = q[2], t3 = q[3];
                xp[0] = t0.x; xp[1] = t0.y;
                xp[2] = t1.x; xp[3] = t1.y;
                xp[4] = t2.x; xp[5] = t2.y;
                xp[6] = t3.x; xp[7] = t3.y;
                xp[8] = xs[warp][bcur][(grp + 2) * 10 + 8];
            }

            u64 a0 = vB0, a1 = vB1, a2 = vB2;
            #pragma unroll
            for (int i = 0; i < 9; i++) {
                a0 = ffma2(w1p[0][i], xp[i], a0);
                a1 = ffma2(w1p[1][i], xp[i], a1);
                a2 = ffma2(w1p[2][i], xp[i], a2);
            }
            float f0, f1;
            upk2(a0, f0, f1);
            u64 s0 = pk2(setgt1(f0), setgt1(f1));
            upk2(a1, f0, f1);
            u64 s1 = pk2(setgt1(f0), setgt1(f1));
            upk2(a2, f0, f1);
            u64 s2 = pk2(setgt1(f0), setgt1(f1));
            vB0 = ffma2(BET2, a0, ffma2(s0, NEG1, b1p[0]));
            vB1 = ffma2(BET2, a1, ffma2(s1, NEG1, b1p[1]));
            vB2 = ffma2(BET2, a2, ffma2(s2, NEG1, b1p[2]));

            u64 c0 = fmul2(s0, w2p[0][0]); c0 = ffma2(s1, w2p[0][1], c0); c0 = ffma2(s2, w2p[0][2], c0);
            u64 c1 = fmul2(s0, w2p[1][0]); c1 = ffma2(s1, w2p[1][1], c1); c1 = ffma2(s2, w2p[1][2], c1);
            u64 c2 = fmul2(s0, w2p[2][0]); c2 = ffma2(s1, w2p[2][1], c2); c2 = ffma2(s2, w2p[2][2], c2);
            float ta, tb;
            upk2(c0, ta, tb); sB0 = ta + tb;
            upk2(c1, ta, tb); sB1 = ta + tb;
            upk2(c2, ta, tb); sB2 = ta + tb;
        }

        // ---- tails interleaved: xor8 then xor4, six independent values ----
        sA0 += __shfl_xor_sync(0xffffffffu, sA0, 8);
        sA1 += __shfl_xor_sync(0xffffffffu, sA1, 8);
        sA2 += __shfl_xor_sync(0xffffffffu, sA2, 8);
        sB0 += __shfl_xor_sync(0xffffffffu, sB0, 8);
        sB1 += __shfl_xor_sync(0xffffffffu, sB1, 8);
        sB2 += __shfl_xor_sync(0xffffffffu, sB2, 8);
        sA0 += __shfl_xor_sync(0xffffffffu, sA0, 4);
        sA1 += __shfl_xor_sync(0xffffffffu, sA1, 4);
        sA2 += __shfl_xor_sync(0xffffffffu, sA2, 4);
        sB0 += __shfl_xor_sync(0xffffffffu, sB0, 4);
        sB1 += __shfl_xor_sync(0xffffffffu, sB1, 4);
        sB2 += __shfl_xor_sync(0xffffffffu, sB2, 4);
        ppA = (oc == 0) ? sA0 : ((oc == 1) ? sA1 : sA2);
        ppB = (oc == 0) ? sB0 : ((oc == 1) ? sB1 : sB2);

        __syncwarp();
        int tmp = bcur; bcur = bnext; bnext = bnn; bnn = tmp;
    }

    // ---- epilogue: timestep T-1 for both sets ----
    {
        float svA = ppA, svB = ppB;
        svA += __shfl_xor_sync(0xffffffffu, svA, 2);
        svB += __shfl_xor_sync(0xffffffffu, svB, 2);
        svA += __shfl_xor_sync(0xffffffffu, svA, 1);
        svB += __shfl_xor_sync(0xffffffffu, svB, 1);
        float mmA = fmaf(BETA, m2A, bias + svA) - spA;
        float mmB = fmaf(BETA, m2B, bias + svB) - spB;
        if (fin_store) {
            __stcs(optr,     is_spk ? setgt1(mmA) : mmA);
            __stcs(optr + 6, is_spk ? setgt1(mmB) : mmB);
        }
    }
}

extern "C" void kernel_launch(void* const* d_in, const int* in_sizes, int n_in,
                              void* d_out, int out_size) {
    const float* x  = (const float*)d_in[0];
    const float* W1 = (const float*)d_in[1];
    const float* b1 = (const float*)d_in[2];
    const float* W2 = (const float*)d_in[3];
    const float* b2 = (const float*)d_in[4];
    float* out = (float*)d_out;

    // 8192 batches / (4 per warp * 2 warps) = 1024 CTAs of 64 threads -> 1 wave
    snn_kernel<<<1024, 64>>>(x, W1, b1, W2, b2, out);
}

// round 12
// speedup vs baseline: 1.0717x; 1.0717x over previous
#include <cuda_runtime.h>

// SNN forward: T=1000, B=8192, I=9, H=96, O=3
// 4 batches/warp (2 independent batch-sets), CTA=64 (2 warps), grid=1024 -> 1 wave.
// v = beta*mem1 + b1 - spk1 fusion; FSET spikes; reduction split across iters.
// x pipeline DEPTH 2: 4-buffer smem ring + two in-flight LDG registers, so the
// DRAM latency of the x prefetch is covered by ~2 iterations instead of 1.

#define T_STEPS 1000
#define BATCHN  8192
#define BETA    0.92f

typedef unsigned long long u64;

static __device__ __forceinline__ u64 pk2(float lo, float hi) {
    u64 r; asm("mov.b64 %0,{%1,%2};" : "=l"(r) : "f"(lo), "f"(hi)); return r;
}
static __device__ __forceinline__ void upk2(u64 v, float& a, float& b) {
    asm("mov.b64 {%0,%1},%2;" : "=f"(a), "=f"(b) : "l"(v));
}
static __device__ __forceinline__ u64 ffma2(u64 a, u64 b, u64 c) {
    u64 d; asm("fma.rn.f32x2 %0,%1,%2,%3;" : "=l"(d) : "l"(a), "l"(b), "l"(c)); return d;
}
static __device__ __forceinline__ u64 fmul2(u64 a, u64 b) {
    u64 d; asm("mul.rn.f32x2 %0,%1,%2;" : "=l"(d) : "l"(a), "l"(b)); return d;
}
static __device__ __forceinline__ float setgt1(float a) {
    float d; asm("set.gt.f32.f32 %0,%1,%2;" : "=f"(d) : "f"(a), "f"(1.0f)); return d;
}

__global__ void __launch_bounds__(64, 7) snn_kernel(
    const float* __restrict__ x,
    const float* __restrict__ W1,
    const float* __restrict__ b1,
    const float* __restrict__ W2,
    const float* __restrict__ b2,
    float* __restrict__ out)
{
    const int lane = threadIdx.x & 31;
    const int warp = threadIdx.x >> 5;
    const int gw   = blockIdx.x * 2 + warp;
    const int grp  = lane >> 4;
    const int hl   = lane & 15;
    const int hb   = hl * 6;
    const int bA   = gw * 4 + grp;               // set-0 batch; set-1 = bA + 2

    // x ring: [warp][4 bufs][4 slots x 10 u64]
    __shared__ __align__(16) u64 xs[2][4][40];

    u64 w1p[3][9];
    #pragma unroll
    for (int j = 0; j < 3; j++)
        #pragma unroll
        for (int i = 0; i < 9; i++)
            w1p[j][i] = pk2(W1[(hb + 2*j) * 9 + i], W1[(hb + 2*j + 1) * 9 + i]);

    u64 w2p[3][3];
    #pragma unroll
    for (int o = 0; o < 3; o++)
        #pragma unroll
        for (int j = 0; j < 3; j++)
            w2p[o][j] = pk2(W2[o * 96 + hb + 2*j], W2[o * 96 + hb + 2*j + 1]);

    u64 b1p[3];
    #pragma unroll
    for (int j = 0; j < 3; j++) b1p[j] = pk2(b1[hb + 2*j], b1[hb + 2*j + 1]);

    const u64 BET2 = pk2(BETA, BETA);
    const u64 NEG1 = pk2(-1.0f, -1.0f);

    const int  oc        = (hl >> 2) > 2 ? 2 : (hl >> 2);
    const bool fin_store = ((hl & 3) < 2) && (hl < 12);
    const bool is_spk    = (hl & 3) == 0;
    const float bias     = b2[oc];

    float* optr = (is_spk ? out : out + (size_t)T_STEPS * BATCHN * 3)
                  + (size_t)bA * 3 + oc;

    u64 vA0 = b1p[0], vA1 = b1p[1], vA2 = b1p[2];
    u64 vB0 = b1p[0], vB1 = b1p[1], vB2 = b1p[2];
    float m2A = 0.f, spA = 0.f, ppA = 0.f;
    float m2B = 0.f, spB = 0.f, ppB = 0.f;

    // ---- x loaders: 36 contiguous floats per warp-step ----
    const int  idx0 = lane;
    const int  off0 = (idx0 / 9) * 10 + idx0 % 9;
    const bool l2   = lane < 4;
    const int  idx1 = 32 + lane;
    const int  off1 = (idx1 / 9) * 10 + idx1 % 9;
    const float* p0 = x + (size_t)gw * 36 + idx0;
    const float* p1 = x + (size_t)gw * 36 + idx1;
    const size_t xstr = (size_t)BATCHN * 9;

    // prologue: buffers 0,1 filled directly; x(2),x(3) in flight in registers
    {
        float v0l = p0[0];
        xs[warp][0][off0] = pk2(v0l, v0l);
        float v1l = p0[xstr];
        xs[warp][1][off0] = pk2(v1l, v1l);
        if (l2) {
            float w0l = p1[0];
            xs[warp][0][off1] = pk2(w0l, w0l);
            float w1l = p1[xstr];
            xs[warp][1][off1] = pk2(w1l, w1l);
        }
    }
    float rEa = p0[2 * xstr];                   // x(2) -> staged at even iter 0
    float rEb = l2 ? p1[2 * xstr] : 0.f;
    float rOa = p0[3 * xstr];                   // x(3) -> staged at odd iter 1
    float rOb = l2 ? p1[3 * xstr] : 0.f;
    __syncwarp();

    #pragma unroll 2
    for (int t = 0; t < T_STEPS; t++) {
        u64* base  = xs[warp][t & 3];
        u64* stage = xs[warp][(t + 2) & 3];

        // ---- stage x(t+2) from the register loaded 2 iters ago; refill x(t+4) ----
        {
            float ra = (t & 1) ? rOa : rEa;
            float rb = (t & 1) ? rOb : rEb;
            stage[off0] = pk2(ra, ra);
            if (l2) stage[off1] = pk2(rb, rb);
            int tn = (t + 4 < T_STEPS) ? (t + 4) : (T_STEPS - 1);
            float na = p0[(size_t)tn * xstr];
            float nb = l2 ? p1[(size_t)tn * xstr] : 0.f;
            if (t & 1) { rOa = na; rOb = nb; } else { rEa = na; rEb = nb; }
        }

        // ---- head: finish previous step's reductions + finalize + store ----
        if (t) {
            float svA = ppA, svB = ppB;
            svA += __shfl_xor_sync(0xffffffffu, svA, 2);
            svB += __shfl_xor_sync(0xffffffffu, svB, 2);
            svA += __shfl_xor_sync(0xffffffffu, svA, 1);
            svB += __shfl_xor_sync(0xffffffffu, svB, 1);
            float mmA = fmaf(BETA, m2A, bias + svA) - spA;  m2A = mmA;
            float mmB = fmaf(BETA, m2B, bias + svB) - spB;  m2B = mmB;
            spA = setgt1(mmA);
            spB = setgt1(mmB);
            if (fin_store) {
                __stcs(optr,     is_spk ? spA : mmA);
                __stcs(optr + 6, is_spk ? spB : mmB);
            }
            optr += 3 * BATCHN;
        }
        __syncwarp();

        float sA0, sA1, sA2, sB0, sB1, sB2;

        // ======== batch set A ========
        {
            u64 xp[9];
            {
                const ulonglong2* q = reinterpret_cast<const ulonglong2*>(base + grp * 10);
                ulonglong2 t0 = q[0], t1 = q[1], t2 = q[2], t3 = q[3];
                xp[0] = t0.x; xp[1] = t0.y;
                xp[2] = t1.x; xp[3] = t1.y;
                xp[4] = t2.x; xp[5] = t2.y;
                xp[6] = t3.x; xp[7] = t3.y;
                xp[8] = base[grp * 10 + 8];
            }
            u64 a0 = vA0, a1 = vA1, a2 = vA2;
            #pragma unroll
            for (int i = 0; i < 9; i++) {
                a0 = ffma2(w1p[0][i], xp[i], a0);
                a1 = ffma2(w1p[1][i], xp[i], a1);
                a2 = ffma2(w1p[2][i], xp[i], a2);
            }
            float f0, f1;
            upk2(a0, f0, f1);
            u64 s0 = pk2(setgt1(f0), setgt1(f1));
            upk2(a1, f0, f1);
            u64 s1 = pk2(setgt1(f0), setgt1(f1));
            upk2(a2, f0, f1);
            u64 s2 = pk2(setgt1(f0), setgt1(f1));
            vA0 = ffma2(BET2, a0, ffma2(s0, NEG1, b1p[0]));
            vA1 = ffma2(BET2, a1, ffma2(s1, NEG1, b1p[1]));
            vA2 = ffma2(BET2, a2, ffma2(s2, NEG1, b1p[2]));

            u64 c0 = fmul2(s0, w2p[0][0]); c0 = ffma2(s1, w2p[0][1], c0); c0 = ffma2(s2, w2p[0][2], c0);
            u64 c1 = fmul2(s0, w2p[1][0]); c1 = ffma2(s1, w2p[1][1], c1); c1 = ffma2(s2, w2p[1][2], c1);
            u64 c2 = fmul2(s0, w2p[2][0]); c2 = ffma2(s1, w2p[2][1], c2); c2 = ffma2(s2, w2p[2][2], c2);
            float ta, tb;
            upk2(c0, ta, tb); sA0 = ta + tb;
            upk2(c1, ta, tb); sA1 = ta + tb;
            upk2(c2, ta, tb); sA2 = ta + tb;
        }

        // ======== batch set B ========
        {
            u64 xp[9];
            {
                const ulonglong2* q = reinterpret_cast<const ulonglong2*>(base + (grp + 2) * 10);
                ulonglong2 t0 = q[0], t1 = q[1], t2 = q[2], t3 = q[3];
                xp[0] = t0.x; xp[1] = t0.y;
                xp[2] = t1.x; xp[3] = t1.y;
                xp[4] = t2.x; xp[5] = t2.y;
                xp[6] = t3.x; xp[7] = t3.y;
                xp[8] = base[(grp + 2) * 10 + 8];
            }
            u64 a0 = vB0, a1 = vB1, a2 = vB2;
            #pragma unroll
            for (int i = 0; i < 9; i++) {
                a0 = ffma2(w1p[0][i], xp[i], a0);
                a1 = ffma2(w1p[1][i], xp[i], a1);
                a2 = ffma2(w1p[2][i], xp[i], a2);
            }
            float f0, f1;
            upk2(a0, f0, f1);
            u64 s0 = pk2(setgt1(f0), setgt1(f1));
            upk2(a1, f0, f1);
            u64 s1 = pk2(setgt1(f0), setgt1(f1));
            upk2(a2, f0, f1);
            u64 s2 = pk2(setgt1(f0), setgt1(f1));
            vB0 = ffma2(BET2, a0, ffma2(s0, NEG1, b1p[0]));
            vB1 = ffma2(BET2, a1, ffma2(s1, NEG1, b1p[1]));
            vB2 = ffma2(BET2, a2, ffma2(s2, NEG1, b1p[2]));

            u64 c0 = fmul2(s0, w2p[0][0]); c0 = ffma2(s1, w2p[0][1], c0); c0 = ffma2(s2, w2p[0][2], c0);
            u64 c1 = fmul2(s0, w2p[1][0]); c1 = ffma2(s1, w2p[1][1], c1); c1 = ffma2(s2, w2p[1][2], c1);
            u64 c2 = fmul2(s0, w2p[2][0]); c2 = ffma2(s1, w2p[2][1], c2); c2 = ffma2(s2, w2p[2][2], c2);
            float ta, tb;
            upk2(c0, ta, tb); sB0 = ta + tb;
            upk2(c1, ta, tb); sB1 = ta + tb;
            upk2(c2, ta, tb); sB2 = ta + tb;
        }

        // ---- tails interleaved: xor8 then xor4 ----
        sA0 += __shfl_xor_sync(0xffffffffu, sA0, 8);
        sA1 += __shfl_xor_sync(0xffffffffu, sA1, 8);
        sA2 += __shfl_xor_sync(0xffffffffu, sA2, 8);
        sB0 += __shfl_xor_sync(0xffffffffu, sB0, 8);
        sB1 += __shfl_xor_sync(0xffffffffu, sB1, 8);
        sB2 += __shfl_xor_sync(0xffffffffu, sB2, 8);
        sA0 += __shfl_xor_sync(0xffffffffu, sA0, 4);
        sA1 += __shfl_xor_sync(0xffffffffu, sA1, 4);
        sA2 += __shfl_xor_sync(0xffffffffu, sA2, 4);
        sB0 += __shfl_xor_sync(0xffffffffu, sB0, 4);
        sB1 += __shfl_xor_sync(0xffffffffu, sB1, 4);
        sB2 += __shfl_xor_sync(0xffffffffu, sB2, 4);
        ppA = (oc == 0) ? sA0 : ((oc == 1) ? sA1 : sA2);
        ppB = (oc == 0) ? sB0 : ((oc == 1) ? sB1 : sB2);
    }

    // ---- epilogue: timestep T-1 ----
    {
        float svA = ppA, svB = ppB;
        svA += __shfl_xor_sync(0xffffffffu, svA, 2);
        svB += __shfl_xor_sync(0xffffffffu, svB, 2);
        svA += __shfl_xor_sync(0xffffffffu, svA, 1);
        svB += __shfl_xor_sync(0xffffffffu, svB, 1);
        float mmA = fmaf(BETA, m2A, bias + svA) - spA;
        float mmB = fmaf(BETA, m2B, bias + svB) - spB;
        if (fin_store) {
            __stcs(optr,     is_spk ? setgt1(mmA) : mmA);
            __stcs(optr + 6, is_spk ? setgt1(mmB) : mmB);
        }
    }
}

extern "C" void kernel_launch(void* const* d_in, const int* in_sizes, int n_in,
                              void* d_out, int out_size) {
    const float* x  = (const float*)d_in[0];
    const float* W1 = (const float*)d_in[1];
    const float* b1 = (const float*)d_in[2];
    const float* W2 = (const float*)d_in[3];
    const float* b2 = (const float*)d_in[4];
    float* out = (float*)d_out;

    snn_kernel<<<1024, 64>>>(x, W1, b1, W2, b2, out);
}